// round 16
// baseline (speedup 1.0000x reference)
#include <cuda_runtime.h>
#include <cstdint>

// Problem dimensions (fixed by the dataset)
#define NN   16000          // nodes
#define F1   256            // layer-1 input features
#define HID  512            // HEADS*OUT
#define NH   8              // heads
#define OC   64             // per-head out channels
#define RR   8              // relations
#define ECAP 300000         // capacity for edges + self loops

// ---------------- scratch (device globals; no allocation allowed) ----------
__device__ float    g_t[(size_t)RR * NN * HID];   // relation-transformed nodes [R,N,512]
__device__ float    g_h[(size_t)NN * HID];        // layer-1 output
__device__ float    g_qk[(size_t)NN * 128];       // [node][r*16 + (q:0-7 | k:8-15)]
__device__ float    g_wqk[(size_t)HID * 128];     // folded W@q / W@k weights
__device__ float    g_ce[NH];                     // (We @ e)[h]
__device__ uint32_t g_At[(size_t)HID * NN];       // tf32 bits, [K][M] m-interleaved
__device__ uint32_t g_Bt[(size_t)RR * HID * HID]; // tf32 bits, [r][k][n]
__device__ int      g_etmax;
__device__ int      g_hist[NN];
__device__ int      g_rowptr[NN + 1];
__device__ int      g_cursor[NN];
__device__ int      g_csr_sr[ECAP];               // src | (rel << 20)
__device__ float    g_csr_attr[ECAP];

// ---------------- helpers ---------------------------------------------------
__device__ __forceinline__ uint32_t f2tf(float f) {
    uint32_t u;
    asm("cvt.rna.tf32.f32 %0, %1;" : "=r"(u) : "f"(f));
    return u;
}
__device__ __forceinline__ void mma_tf32(float c[4], const uint32_t a[4], const uint32_t b[2]) {
    asm volatile("mma.sync.aligned.m16n8k8.row.col.f32.tf32.tf32.f32 "
                 "{%0,%1,%2,%3}, {%4,%5,%6,%7}, {%8,%9}, {%0,%1,%2,%3};"
                 : "+f"(c[0]), "+f"(c[1]), "+f"(c[2]), "+f"(c[3])
                 : "r"(a[0]), "r"(a[1]), "r"(a[2]), "r"(a[3]), "r"(b[0]), "r"(b[1]));
}
__device__ __forceinline__ uint32_t s2u(const void* p) {
    uint32_t a;
    asm("{.reg .u64 t; cvta.to.shared.u64 t, %1; cvt.u32.u64 %0, t;}" : "=r"(a) : "l"(p));
    return a;
}
__device__ __forceinline__ void cp16(uint32_t saddr, const void* g) {
    asm volatile("cp.async.cg.shared.global [%0], [%1], 16;" :: "r"(saddr), "l"(g));
}
#define CP_COMMIT() asm volatile("cp.async.commit_group;")
#define CP_WAIT1()  asm volatile("cp.async.wait_group 1;")

// ---------------- CSR build --------------------------------------------------
__global__ void init_kernel() {
    int i = blockIdx.x * blockDim.x + threadIdx.x;
    if (i < NN) g_hist[i] = 0;
    if (i == 0) g_etmax = 0;
}

__global__ void etmax_kernel(const int* __restrict__ et, int E0) {
    int i = blockIdx.x * blockDim.x + threadIdx.x;
    int loc = -1;
    for (; i < E0; i += gridDim.x * blockDim.x) loc = max(loc, et[i]);
    if (loc >= 0) atomicMax(&g_etmax, loc);
}

__global__ void hist_kernel(const int* __restrict__ ei, int E0, int Etot) {
    int e = blockIdx.x * blockDim.x + threadIdx.x;
    if (e >= Etot) return;
    int d = (e < E0) ? ei[E0 + e] : (e - E0);
    atomicAdd(&g_hist[d], 1);
}

__global__ __launch_bounds__(1024)
void scan_kernel() {
    __shared__ int sm[1024];
    const int t = threadIdx.x;
    const int base = t * 16;
    int loc[16];
    int sum = 0;
#pragma unroll
    for (int i = 0; i < 16; i++) {
        int idx = base + i;
        int v = (idx < NN) ? g_hist[idx] : 0;
        loc[i] = sum;
        sum += v;
    }
    sm[t] = sum;
    __syncthreads();
    for (int off = 1; off < 1024; off <<= 1) {
        int v = (t >= off) ? sm[t - off] : 0;
        __syncthreads();
        sm[t] += v;
        __syncthreads();
    }
    int pre = (t > 0) ? sm[t - 1] : 0;
#pragma unroll
    for (int i = 0; i < 16; i++) {
        int idx = base + i;
        if (idx < NN) {
            g_rowptr[idx] = pre + loc[i];
            g_cursor[idx] = pre + loc[i];
        }
    }
    if (t == 1023) g_rowptr[NN] = sm[1023];
}

__global__ void scatter_kernel(const int* __restrict__ ei, const int* __restrict__ etyp,
                               const float* __restrict__ ea, int E0, int Etot) {
    int e = blockIdx.x * blockDim.x + threadIdx.x;
    if (e >= Etot) return;
    int s, d, r;  float at;
    if (e < E0) { s = ei[e]; d = ei[E0 + e]; r = etyp[e]; at = ea[e]; }
    else        { s = d = e - E0; r = (g_etmax + 1) & (RR - 1); at = 0.5f; }
    int p = atomicAdd(&g_cursor[d], 1);
    g_csr_sr[p]   = s | (r << 20);
    g_csr_attr[p] = at;
}

// ---------------- operand conversion ----------------------------------------
// A: [M][K] fp32 -> g_At [K][M] tf32 bits, m-interleaved within 16-groups.
__global__ __launch_bounds__(256)
void convA_kernel(const float* __restrict__ A, int K) {
    __shared__ float sm[32][33];
    const int tx = threadIdx.x & 31, ty = threadIdx.x >> 5;   // 32 x 8
    const int k0 = blockIdx.x * 32, m0 = blockIdx.y * 32;
#pragma unroll
    for (int j = 0; j < 4; j++)
        sm[ty + 8 * j][tx] = A[(size_t)(m0 + ty + 8 * j) * K + k0 + tx];
    __syncthreads();
    const int lm   = m0 + tx;
    const int mperm = (lm & ~15) | (((lm & 7) << 1) | ((lm >> 3) & 1));
#pragma unroll
    for (int j = 0; j < 4; j++)
        g_At[(size_t)(k0 + ty + 8 * j) * NN + mperm] = f2tf(sm[tx][ty + 8 * j]);
}

// B: elementwise fp32 -> tf32 bits (layout unchanged)
__global__ __launch_bounds__(256)
void convB_kernel(const float* __restrict__ B, int n) {
    int i = blockIdx.x * blockDim.x + threadIdx.x;
    if (i < n) g_Bt[i] = f2tf(B[i]);
}

// ===== cp.async GEMM: 128x128 block, 64x32 warp tiles, BK=32, 2 CTAs/SM =====
// 8 warps = 2(m) x 4(n). 3 stages x BK=32, ONE __syncthreads per iteration.
// As [k][m-int] stride 136; Bs [k][n] stride 136 (== 8 mod 32). tf32 pre-conv.
#define GSMEM_WORDS (3 * 32 * 136 * 2)
__global__ __launch_bounds__(256, 2)
void gemm_cp_kernel(float* __restrict__ C0, int K, int rstrideB, int rstrideC) {
    extern __shared__ __align__(16) uint32_t smem[];
    uint32_t (*As)[32][136] = (uint32_t (*)[32][136])smem;
    uint32_t (*Bs)[32][136] = (uint32_t (*)[32][136])(smem + 3 * 32 * 136);

    const int r  = blockIdx.x >> 2;
    const int n0 = (blockIdx.x & 3) * 128;
    const int m0 = blockIdx.y * 128;
    const uint32_t* Bt = g_Bt + (size_t)r * rstrideB;
    float*          C  = C0 + (size_t)r * rstrideC;

    const int tid  = threadIdx.x;
    const int lane = tid & 31, warp = tid >> 5;
    const int grp  = lane >> 2, tig = lane & 3;
    const int wm   = (warp & 1) * 64;
    const int wn   = (warp >> 1) * 32;

    // loader mapping: 256 threads cover 32x128 words via 4 passes of 8 rows
    const int arow = tid >> 5;          // 0..7
    const int acol = (tid & 31) * 4;    // 0..124

    const uint32_t* Ag = g_At + (size_t)arow * NN + m0 + acol;
    const uint32_t* Bg = Bt  + (size_t)arow * 512 + n0 + acol;

    uint32_t sA[3], sB[3];
#pragma unroll
    for (int st = 0; st < 3; st++) {
        sA[st] = s2u(&As[st][arow][acol]);
        sB[st] = s2u(&Bs[st][arow][acol]);
    }
    const int JSTRIDE = 8 * 136 * 4;    // 8 rows in bytes

    float c[4][4][4];
#pragma unroll
    for (int mt = 0; mt < 4; mt++)
#pragma unroll
        for (int nt = 0; nt < 4; nt++)
#pragma unroll
            for (int i = 0; i < 4; i++) c[mt][nt][i] = 0.f;

    const int NSTEP = K >> 5;
    // prologue: stages 0,1
#pragma unroll
    for (int st = 0; st < 2; st++) {
        const size_t k0 = (size_t)st * 32;
#pragma unroll
        for (int j = 0; j < 4; j++) {
            cp16(sA[st] + j * JSTRIDE, Ag + (k0 + 8 * j) * NN);
            cp16(sB[st] + j * JSTRIDE, Bg + (k0 + 8 * j) * 512);
        }
        CP_COMMIT();
    }

    int buf = 0;
    for (int s = 0; s < NSTEP; s++) {
        CP_WAIT1();
        __syncthreads();        // stage s ready; all warps done with stage s-1
        if (s + 2 < NSTEP) {
            const int st = (s + 2) % 3;
            const size_t k0 = (size_t)(s + 2) * 32;
#pragma unroll
            for (int j = 0; j < 4; j++) {
                cp16(sA[st] + j * JSTRIDE, Ag + (k0 + 8 * j) * NN);
                cp16(sB[st] + j * JSTRIDE, Bg + (k0 + 8 * j) * 512);
            }
        }
        CP_COMMIT();            // commit every iter keeps group count in sync

#pragma unroll
        for (int kb = 0; kb < 32; kb += 8) {
            uint32_t af[4][4], bf[4][2];
#pragma unroll
            for (int mt = 0; mt < 4; mt++) {
                const int mcol = wm + mt * 16 + 2 * grp;
                const uint2 p0 = *(const uint2*)&As[buf][kb + tig][mcol];
                const uint2 p1 = *(const uint2*)&As[buf][kb + tig + 4][mcol];
                af[mt][0] = p0.x; af[mt][1] = p0.y;
                af[mt][2] = p1.x; af[mt][3] = p1.y;
            }
#pragma unroll
            for (int nt = 0; nt < 4; nt++) {
                const int nc = wn + nt * 8 + grp;
                bf[nt][0] = Bs[buf][kb + tig][nc];
                bf[nt][1] = Bs[buf][kb + tig + 4][nc];
            }
#pragma unroll
            for (int mt = 0; mt < 4; mt++)
#pragma unroll
                for (int nt = 0; nt < 4; nt++)
                    mma_tf32(c[mt][nt], af[mt], bf[nt]);
        }
        buf = (buf + 1 == 3) ? 0 : buf + 1;
    }

#pragma unroll
    for (int mt = 0; mt < 4; mt++) {
        const int row = m0 + wm + mt * 16 + grp;
#pragma unroll
        for (int nt = 0; nt < 4; nt++) {
            const int col = n0 + wn + nt * 8 + tig * 2;
            *(float2*)(C + (size_t)row * 512 + col)       = make_float2(c[mt][nt][0], c[mt][nt][1]);
            *(float2*)(C + (size_t)(row + 8) * 512 + col) = make_float2(c[mt][nt][2], c[mt][nt][3]);
        }
    }
}

// ---------------- narrow GEMM (128x128) for q/k projection -------------------
__device__ __forceinline__ void gemm_tf32_body(
    const float* __restrict__ A, const float* __restrict__ B,
    float* __restrict__ C, int K, int m0, int n0, int ldb, int ldc)
{
    __shared__ __align__(16) uint32_t As[2][16][136];
    __shared__ __align__(16) uint32_t Bs[2][16][136];

    const int tid  = threadIdx.x;
    const int lane = tid & 31, warp = tid >> 5;
    const int grp  = lane >> 2, tig = lane & 3;
    const int wm   = (warp & 3) * 32;
    const int wn   = (warp >> 2) * 64;

    const int am   = tid & 127;
    const int amp  = (am & 0x70) | ((am & 7) << 1) | ((am >> 3) & 1);
    const int akq0 = tid >> 7;
    const int akq1 = akq0 + 2;
    const int bn4  = tid & 31;
    const int bk0  = tid >> 5;
    const int bk1  = bk0 + 8;

    const float* Ag0 = A + (size_t)(m0 + am) * K + 4 * akq0;
    const float* Ag1 = A + (size_t)(m0 + am) * K + 4 * akq1;
    const float* Bg0 = B + (size_t)bk0 * ldb + n0 + 4 * bn4;
    const float* Bg1 = B + (size_t)bk1 * ldb + n0 + 4 * bn4;

    float c[2][8][4];
#pragma unroll
    for (int mt = 0; mt < 2; mt++)
#pragma unroll
        for (int nt = 0; nt < 8; nt++)
#pragma unroll
            for (int i = 0; i < 4; i++) c[mt][nt][i] = 0.f;

    float4 a0v = *(const float4*)Ag0;
    float4 a1v = *(const float4*)Ag1;
    float4 b0v = *(const float4*)Bg0;
    float4 b1v = *(const float4*)Bg1;
    As[0][4 * akq0 + 0][amp] = f2tf(a0v.x); As[0][4 * akq0 + 1][amp] = f2tf(a0v.y);
    As[0][4 * akq0 + 2][amp] = f2tf(a0v.z); As[0][4 * akq0 + 3][amp] = f2tf(a0v.w);
    As[0][4 * akq1 + 0][amp] = f2tf(a1v.x); As[0][4 * akq1 + 1][amp] = f2tf(a1v.y);
    As[0][4 * akq1 + 2][amp] = f2tf(a1v.z); As[0][4 * akq1 + 3][amp] = f2tf(a1v.w);
    *(uint4*)&Bs[0][bk0][4 * bn4] = make_uint4(f2tf(b0v.x), f2tf(b0v.y), f2tf(b0v.z), f2tf(b0v.w));
    *(uint4*)&Bs[0][bk1][4 * bn4] = make_uint4(f2tf(b1v.x), f2tf(b1v.y), f2tf(b1v.z), f2tf(b1v.w));
    __syncthreads();

    int buf = 0;
    const int NSTEP = K >> 4;
    for (int s = 0; s < NSTEP; s++) {
        const bool nxt = (s + 1) < NSTEP;
        if (nxt) {
            const int ko = (s + 1) << 4;
            a0v = *(const float4*)(Ag0 + ko);
            a1v = *(const float4*)(Ag1 + ko);
            b0v = *(const float4*)(Bg0 + (size_t)ko * ldb);
            b1v = *(const float4*)(Bg1 + (size_t)ko * ldb);
        }
#pragma unroll
        for (int kb = 0; kb < 16; kb += 8) {
            uint32_t af[2][4], bf[8][2];
#pragma unroll
            for (int mt = 0; mt < 2; mt++) {
                const int mcol = wm + mt * 16 + 2 * grp;
                const uint2 p0 = *(const uint2*)&As[buf][kb + tig][mcol];
                const uint2 p1 = *(const uint2*)&As[buf][kb + tig + 4][mcol];
                af[mt][0] = p0.x; af[mt][1] = p0.y;
                af[mt][2] = p1.x; af[mt][3] = p1.y;
            }
#pragma unroll
            for (int nt = 0; nt < 8; nt++) {
                const int nc = wn + nt * 8 + grp;
                bf[nt][0] = Bs[buf][kb + tig][nc];
                bf[nt][1] = Bs[buf][kb + tig + 4][nc];
            }
#pragma unroll
            for (int mt = 0; mt < 2; mt++)
#pragma unroll
                for (int nt = 0; nt < 8; nt++)
                    mma_tf32(c[mt][nt], af[mt], bf[nt]);
        }
        if (nxt) {
            const int nb = buf ^ 1;
            As[nb][4 * akq0 + 0][amp] = f2tf(a0v.x); As[nb][4 * akq0 + 1][amp] = f2tf(a0v.y);
            As[nb][4 * akq0 + 2][amp] = f2tf(a0v.z); As[nb][4 * akq0 + 3][amp] = f2tf(a0v.w);
            As[nb][4 * akq1 + 0][amp] = f2tf(a1v.x); As[nb][4 * akq1 + 1][amp] = f2tf(a1v.y);
            As[nb][4 * akq1 + 2][amp] = f2tf(a1v.z); As[nb][4 * akq1 + 3][amp] = f2tf(a1v.w);
            *(uint4*)&Bs[nb][bk0][4 * bn4] = make_uint4(f2tf(b0v.x), f2tf(b0v.y), f2tf(b0v.z), f2tf(b0v.w));
            *(uint4*)&Bs[nb][bk1][4 * bn4] = make_uint4(f2tf(b1v.x), f2tf(b1v.y), f2tf(b1v.z), f2tf(b1v.w));
            __syncthreads();
            buf = nb;
        }
    }

#pragma unroll
    for (int mt = 0; mt < 2; mt++) {
        const int row = m0 + wm + mt * 16 + grp;
#pragma unroll
        for (int nt = 0; nt < 8; nt++) {
            const int col = n0 + wn + nt * 8 + tig * 2;
            *(float2*)(C + (size_t)row * ldc + col)       = make_float2(c[mt][nt][0], c[mt][nt][1]);
            *(float2*)(C + (size_t)(row + 8) * ldc + col) = make_float2(c[mt][nt][2], c[mt][nt][3]);
        }
    }
}

// q/k projection GEMM: [NN x K] @ [K x 128] -> g_qk [NN x 128]
__global__ __launch_bounds__(256, 2)
void qkgemm_l1_kernel(const float* __restrict__ A, int K) {
    gemm_tf32_body(A, g_wqk, g_qk, K, blockIdx.y * 128, 0, 128, 128);
}
__global__ __launch_bounds__(256, 2)
void qkgemm_l2_kernel(int K) {
    gemm_tf32_body(g_h, g_wqk, g_qk, K, blockIdx.y * 128, 0, 128, 128);
}

// ---------------- fold weights: g_wqk[j][r*16+h]=W[r]@q, +8: W[r]@k ----------
__global__ __launch_bounds__(256)
void packqk_kernel(const float* __restrict__ W, const float* __restrict__ q,
                   const float* __restrict__ k, int K) {
    const int gw = (blockIdx.x * blockDim.x + threadIdx.x) >> 5;
    if (gw >= RR * K) return;
    const int r = gw / K, j = gw - r * K;
    const int lane = threadIdx.x & 31;
    const float4* w4 = (const float4*)(W + ((size_t)r * K + j) * HID);
    const float4* q4 = (const float4*)q;
    const float4* k4 = (const float4*)k;
    float aq[NH], ak[NH];
#pragma unroll
    for (int h = 0; h < NH; h++) { aq[h] = 0.f; ak[h] = 0.f; }
#pragma unroll
    for (int i = 0; i < 4; i++) {
        const int c4 = lane + 32 * i;
        const float4 wv = w4[c4];
        const float wa[4] = {wv.x, wv.y, wv.z, wv.w};
#pragma unroll
        for (int f = 0; f < 4; f++) {
            const int c = 4 * c4 + f;
            const float4 qa = q4[c * 2], qb = q4[c * 2 + 1];
            const float4 ka = k4[c * 2], kb = k4[c * 2 + 1];
            const float w = wa[f];
            aq[0] += w * qa.x; aq[1] += w * qa.y; aq[2] += w * qa.z; aq[3] += w * qa.w;
            aq[4] += w * qb.x; aq[5] += w * qb.y; aq[6] += w * qb.z; aq[7] += w * qb.w;
            ak[0] += w * ka.x; ak[1] += w * ka.y; ak[2] += w * ka.z; ak[3] += w * ka.w;
            ak[4] += w * kb.x; ak[5] += w * kb.y; ak[6] += w * kb.z; ak[7] += w * kb.w;
        }
    }
#pragma unroll
    for (int h = 0; h < NH; h++) {
#pragma unroll
        for (int o = 16; o; o >>= 1) {
            aq[h] += __shfl_xor_sync(0xffffffffu, aq[h], o);
            ak[h] += __shfl_xor_sync(0xffffffffu, ak[h], o);
        }
    }
    if (lane == 0) {
        float* dst = g_wqk + (size_t)j * 128 + r * 16;
#pragma unroll
        for (int h = 0; h < NH; h++) {
            dst[h]      = aq[h];
            dst[8 + h]  = ak[h];
        }
    }
}

// ---------------- ce[h] = sum_j We[j] * e[j][h] (warp per head) --------------
__global__ void ce_kernel(const float* __restrict__ We, const float* __restrict__ e) {
    const int warp = threadIdx.x >> 5, lane = threadIdx.x & 31;
    float s = 0.f;
    for (int j = lane; j < HID; j += 32) s += We[j] * e[j * NH + warp];
#pragma unroll
    for (int o = 16; o; o >>= 1) s += __shfl_xor_sync(0xffffffffu, s, o);
    if (lane == 0) g_ce[warp] = s;
}

// ---------------- fused softmax + aggregation: warp per destination ----------
// Phase A computes logits once and stashes them in smem (cap 128 edges/warp;
// statistically never exceeded for random graphs; fallback recomputes).
// A conversion sweep turns them into final weights; phase B is a pure gather.
#define FCAP 128
__global__ __launch_bounds__(256)
void fagg_kernel(const float* __restrict__ b, float* __restrict__ out, int concat) {
    __shared__ float swmem[8][FCAP * 8];
    const int d = (blockIdx.x * blockDim.x + threadIdx.x) >> 5;
    if (d >= NN) return;
    const int lane = threadIdx.x & 31;
    float* swp = swmem[(threadIdx.x >> 5)];
    const int h  = lane & 7;
    const int eg = lane >> 3;
    const int roff = g_rowptr[d];
    const int deg  = g_rowptr[d + 1] - roff;
    const float ceh = g_ce[h];
    const float* qrow = g_qk + (size_t)d * 128;
    float qv[RR];
#pragma unroll
    for (int r = 0; r < RR; r++) qv[r] = qrow[r * 16 + h];

    // ---- phase A: per-head online softmax stats; stash logits ----
    float m = -1e30f, s = 0.f;
    for (int base = 0; base < deg; base += 4) {
        const int e = base + eg;
        if (e < deg) {
            const int   sr = g_csr_sr[roff + e];
            const float at = g_csr_attr[roff + e];
            const int src = sr & 0xFFFFF, r = sr >> 20;
            float l = qv[r] + g_qk[(size_t)src * 128 + r * 16 + 8 + h] + at * ceh;
            l = (l >= 0.f) ? l : 0.2f * l;
            if (e < FCAP) swp[e * 8 + h] = l;
            const float mn = fmaxf(m, l);
            s = s * __expf(m - mn) + __expf(l - mn);
            m = mn;
        }
    }
#pragma unroll
    for (int off = 8; off < 32; off <<= 1) {
        const float om = __shfl_xor_sync(0xffffffffu, m, off);
        const float os = __shfl_xor_sync(0xffffffffu, s, off);
        const float mn = fmaxf(m, om);
        s = s * __expf(m - mn) + os * __expf(om - mn);
        m = mn;
    }
    const float sinv = 1.f / (s + 1e-16f);

    // ---- convert logits -> weights in smem ----
    const int fast = (deg < FCAP) ? deg : FCAP;
    for (int base = 0; base < fast; base += 4) {
        const int e = base + eg;
        if (e < fast) swp[e * 8 + h] = __expf(swp[e * 8 + h] - m) * sinv;
    }
    __syncwarp();

    // ---- phase B: pure weighted gather (2-edge unroll) ----
    float4 a0 = make_float4(0, 0, 0, 0), a1 = a0, a2 = a0, a3 = a0;
    const int hw0 = lane >> 4;
    int e = 0;
    for (; e + 2 <= fast; e += 2) {
        const int sr0 = g_csr_sr[roff + e];
        const int sr1 = g_csr_sr[roff + e + 1];
        const int s0 = sr0 & 0xFFFFF, r0 = sr0 >> 20;
        const int s1 = sr1 & 0xFFFFF, r1 = sr1 >> 20;
        const float* wp0 = swp + e * 8 + hw0;
        const float* wp1 = wp0 + 8;
        const float4* ta = (const float4*)(g_t + ((size_t)r0 * NN + s0) * HID);
        const float4* tb = (const float4*)(g_t + ((size_t)r1 * NN + s1) * HID);
        const float4 u0 = ta[lane], u1 = ta[lane + 32], u2 = ta[lane + 64], u3 = ta[lane + 96];
        const float4 v0 = tb[lane], v1 = tb[lane + 32], v2 = tb[lane + 64], v3 = tb[lane + 96];
        const float wa0 = wp0[0], wa1 = wp0[2], wa2 = wp0[4], wa3 = wp0[6];
        const float wb0 = wp1[0], wb1 = wp1[2], wb2 = wp1[4], wb3 = wp1[6];
        a0.x += wa0 * u0.x + wb0 * v0.x; a0.y += wa0 * u0.y + wb0 * v0.y;
        a0.z += wa0 * u0.z + wb0 * v0.z; a0.w += wa0 * u0.w + wb0 * v0.w;
        a1.x += wa1 * u1.x + wb1 * v1.x; a1.y += wa1 * u1.y + wb1 * v1.y;
        a1.z += wa1 * u1.z + wb1 * v1.z; a1.w += wa1 * u1.w + wb1 * v1.w;
        a2.x += wa2 * u2.x + wb2 * v2.x; a2.y += wa2 * u2.y + wb2 * v2.y;
        a2.z += wa2 * u2.z + wb2 * v2.z; a2.w += wa2 * u2.w + wb2 * v2.w;
        a3.x += wa3 * u3.x + wb3 * v3.x; a3.y += wa3 * u3.y + wb3 * v3.y;
        a3.z += wa3 * u3.z + wb3 * v3.z; a3.w += wa3 * u3.w + wb3 * v3.w;
    }
    for (; e < fast; e++) {
        const int sr = g_csr_sr[roff + e];
        const int src = sr & 0xFFFFF, r = sr >> 20;
        const float* wp = swp + e * 8 + hw0;
        const float4* t4 = (const float4*)(g_t + ((size_t)r * NN + src) * HID);
        const float4 t0 = t4[lane], t1 = t4[lane + 32], t2 = t4[lane + 64], t3 = t4[lane + 96];
        const float w0 = wp[0], w1 = wp[2], w2 = wp[4], w3 = wp[6];
        a0.x += w0 * t0.x; a0.y += w0 * t0.y; a0.z += w0 * t0.z; a0.w += w0 * t0.w;
        a1.x += w1 * t1.x; a1.y += w1 * t1.y; a1.z += w1 * t1.z; a1.w += w1 * t1.w;
        a2.x += w2 * t2.x; a2.y += w2 * t2.y; a2.z += w2 * t2.z; a2.w += w2 * t2.w;
        a3.x += w3 * t3.x; a3.y += w3 * t3.y; a3.z += w3 * t3.z; a3.w += w3 * t3.w;
    }
    // overflow fallback (deg > FCAP): recompute logits, old shfl path
    for (; e < deg; e++) {
        const int   sr = g_csr_sr[roff + e];
        const float at = g_csr_attr[roff + e];
        const int src = sr & 0xFFFFF, r = sr >> 20;
        float l = qv[r] + g_qk[(size_t)src * 128 + r * 16 + 8 + h] + at * ceh;
        l = (l >= 0.f) ? l : 0.2f * l;
        const float w = __expf(l - m) * sinv;
        const float w0 = __shfl_sync(0xffffffffu, w, hw0);
        const float w1 = __shfl_sync(0xffffffffu, w, hw0 + 2);
        const float w2 = __shfl_sync(0xffffffffu, w, hw0 + 4);
        const float w3 = __shfl_sync(0xffffffffu, w, hw0 + 6);
        const float4* t4 = (const float4*)(g_t + ((size_t)r * NN + src) * HID);
        const float4 t0 = t4[lane], t1 = t4[lane + 32], t2 = t4[lane + 64], t3 = t4[lane + 96];
        a0.x += w0 * t0.x; a0.y += w0 * t0.y; a0.z += w0 * t0.z; a0.w += w0 * t0.w;
        a1.x += w1 * t1.x; a1.y += w1 * t1.y; a1.z += w1 * t1.z; a1.w += w1 * t1.w;
        a2.x += w2 * t2.x; a2.y += w2 * t2.y; a2.z += w2 * t2.z; a2.w += w2 * t2.w;
        a3.x += w3 * t3.x; a3.y += w3 * t3.y; a3.z += w3 * t3.z; a3.w += w3 * t3.w;
    }

    if (concat) {
        const float4* b4 = (const float4*)b;
        float4* o4 = (float4*)(g_h + (size_t)d * HID);
        float4 v;
        v = b4[lane];      o4[lane]      = make_float4(a0.x + v.x, a0.y + v.y, a0.z + v.z, a0.w + v.w);
        v = b4[lane + 32]; o4[lane + 32] = make_float4(a1.x + v.x, a1.y + v.y, a1.z + v.z, a1.w + v.w);
        v = b4[lane + 64]; o4[lane + 64] = make_float4(a2.x + v.x, a2.y + v.y, a2.z + v.z, a2.w + v.w);
        v = b4[lane + 96]; o4[lane + 96] = make_float4(a3.x + v.x, a3.y + v.y, a3.z + v.z, a3.w + v.w);
    } else {
        float4 s1 = make_float4(a0.x + a1.x + a2.x + a3.x,
                                a0.y + a1.y + a2.y + a3.y,
                                a0.z + a1.z + a2.z + a3.z,
                                a0.w + a1.w + a2.w + a3.w);
        s1.x += __shfl_xor_sync(0xffffffffu, s1.x, 16);
        s1.y += __shfl_xor_sync(0xffffffffu, s1.y, 16);
        s1.z += __shfl_xor_sync(0xffffffffu, s1.z, 16);
        s1.w += __shfl_xor_sync(0xffffffffu, s1.w, 16);
        if (lane < 16) {
            const float4 bv = ((const float4*)b)[lane];
            ((float4*)(out + (size_t)d * OC))[lane] =
                make_float4(s1.x * 0.125f + bv.x, s1.y * 0.125f + bv.y,
                            s1.z * 0.125f + bv.z, s1.w * 0.125f + bv.w);
        }
    }
}

// ---------------- host driver ------------------------------------------------
extern "C" void kernel_launch(void* const* d_in, const int* in_sizes, int n_in,
                              void* d_out, int out_size) {
    const float* x   = (const float*)d_in[0];
    const int*   ei  = (const int*)  d_in[1];
    const int*   ety = (const int*)  d_in[2];
    const float* ea  = (const float*)d_in[3];
    const float* W1  = (const float*)d_in[4];
    const float* q1  = (const float*)d_in[5];
    const float* k1  = (const float*)d_in[6];
    const float* We1 = (const float*)d_in[7];
    const float* e1  = (const float*)d_in[8];
    const float* b1  = (const float*)d_in[9];
    const float* W2  = (const float*)d_in[10];
    const float* q2  = (const float*)d_in[11];
    const float* k2  = (const float*)d_in[12];
    const float* We2 = (const float*)d_in[13];
    const float* e2  = (const float*)d_in[14];
    const float* b2  = (const float*)d_in[15];

    const int E0   = in_sizes[2];
    const int Etot = E0 + NN;

    float *p_t = nullptr, *p_h = nullptr;
    cudaGetSymbolAddress((void**)&p_t, g_t);
    cudaGetSymbolAddress((void**)&p_h, g_h);

    const int GS = GSMEM_WORDS * 4;   // 104448 bytes dynamic smem
    cudaFuncSetAttribute(gemm_cp_kernel,
                         cudaFuncAttributeMaxDynamicSharedMemorySize, GS);

    const dim3 gw(4 * RR, NN / 128);       // cp GEMM: (n_tile | r<<2, m_tile)
    const dim3 gq(1, NN / 128);
    const int  eB   = (Etot + 255) / 256;
    const int  fagB = (NN * 32) / 256;

    // ---------------- layer 1 (concat); gemm_cp at launch index 3 for ncu ----
    convA_kernel<<<dim3(F1 / 32, NN / 32), 256>>>(x, F1);
    convB_kernel<<<(RR * F1 * HID + 255) / 256, 256>>>(W1, RR * F1 * HID);
    init_kernel<<<(NN + 255) / 256, 256>>>();
    gemm_cp_kernel<<<gw, 256, GS>>>(p_t, F1, F1 * HID, NN * HID);
    etmax_kernel<<<256, 256>>>(ety, E0);
    hist_kernel<<<eB, 256>>>(ei, E0, Etot);
    scan_kernel<<<1, 1024>>>();
    scatter_kernel<<<eB, 256>>>(ei, ety, ea, E0, Etot);
    packqk_kernel<<<RR * F1 / 8, 256>>>(W1, q1, k1, F1);
    ce_kernel<<<1, 256>>>(We1, e1);
    qkgemm_l1_kernel<<<gq, 256>>>(x, F1);
    fagg_kernel<<<fagB, 256>>>(b1, nullptr, 1);

    // ---------------- layer 2 (mean) ------------------
    convA_kernel<<<dim3(HID / 32, NN / 32), 256>>>(p_h, HID);
    convB_kernel<<<(RR * HID * HID + 255) / 256, 256>>>(W2, RR * HID * HID);
    gemm_cp_kernel<<<gw, 256, GS>>>(p_t, HID, HID * HID, NN * HID);
    packqk_kernel<<<RR * HID / 8, 256>>>(W2, q2, k2, HID);
    ce_kernel<<<1, 256>>>(We2, e2);
    qkgemm_l2_kernel<<<gq, 256>>>(HID);
    fagg_kernel<<<fagB, 256>>>(b2, (float*)d_out, 0);
}